// round 11
// baseline (speedup 1.0000x reference)
#include <cuda_runtime.h>
#include <cuda_fp16.h>
#include <math.h>
#include <stdint.h>

#define BD 2
#define NPTS 8192
#define MM 16
#define HH 256
#define CC 128
#define ITEMS (BD*NPTS*MM)
#define TILE 128
#define NBLK (ITEMS/TILE)        // 2048
#define LDA 264                  // A smem row stride (fp16 elements)
#define LDB 40                   // W chunk row stride (fp16 elements)

// smem offsets (bytes)
#define A_OFF    0               // 128*264*2 = 67584
#define WBUF_OFF 67584           // 3 x 40960 = 122880
#define WP_OFF   190464          // 3*256*4
#define BP_OFF   193536
#define B1_OFF   194560
#define B2_OFF   195584
#define WO_OFF   196608
#define XT_OFF   197632          // 128*3*4
#define FELL_OFF 199168
#define MI_OFF   199680
#define SP_OFF   200192          // 128*4*4
#define SMEM_BYTES 202240

__device__ float g_cond[BD*MM*HH];   // [bm][j]
__device__ float g_R[BD*MM*9];
// W fp16: [layer][part(hi/lo)][n][k]; layer stride 262144B, part 131072B, n-row 512B
__device__ __align__(16) unsigned char g_Wh[2*2*256*256*2];

// ---------------- PTX helpers ----------------
__device__ __forceinline__ uint32_t smem_u32(const void* p){
    uint32_t a;
    asm("{ .reg .u64 t; cvta.to.shared.u64 t, %1; cvt.u32.u64 %0, t; }":"=r"(a):"l"(p));
    return a;
}
__device__ __forceinline__ void ldsm4(uint32_t* r, uint32_t addr){
    asm volatile("ldmatrix.sync.aligned.m8n8.x4.shared.b16 {%0,%1,%2,%3}, [%4];"
        : "=r"(r[0]),"=r"(r[1]),"=r"(r[2]),"=r"(r[3]) : "r"(addr));
}
__device__ __forceinline__ void mma16816(float* d, const uint32_t* a, uint32_t b0, uint32_t b1){
    asm volatile("mma.sync.aligned.m16n8k16.row.col.f32.f16.f16.f32 "
        "{%0,%1,%2,%3}, {%4,%5,%6,%7}, {%8,%9}, {%0,%1,%2,%3};"
        : "+f"(d[0]),"+f"(d[1]),"+f"(d[2]),"+f"(d[3])
        : "r"(a[0]),"r"(a[1]),"r"(a[2]),"r"(a[3]), "r"(b0),"r"(b1));
}

// ---------------- prologues ----------------
__global__ void precompute_kernel(const float* __restrict__ rotations,
                                  const float* __restrict__ psf,
                                  const float* __restrict__ Wc,
                                  const float* __restrict__ bc)
{
    __shared__ float s_psf[CC];
    const int bm = blockIdx.x, t = threadIdx.x;
    if (t < CC) s_psf[t] = psf[bm*CC + t];
    __syncthreads();
    float acc = bc[t];
#pragma unroll 8
    for (int k = 0; k < CC; ++k) acc = fmaf(s_psf[k], Wc[k*HH + t], acc);
    g_cond[bm*HH + t] = acc;
    if (t == 0) {
        float w=rotations[bm*4],x=rotations[bm*4+1],y=rotations[bm*4+2],z=rotations[bm*4+3];
        float inv = rsqrtf(w*w+x*x+y*y+z*z);
        w*=inv; x*=inv; y*=inv; z*=inv;
        float* R = g_R + bm*9;
        R[0]=1.f-2.f*(y*y+z*z); R[1]=2.f*(x*y-w*z); R[2]=2.f*(x*z+w*y);
        R[3]=2.f*(x*y+w*z); R[4]=1.f-2.f*(x*x+z*z); R[5]=2.f*(y*z-w*x);
        R[6]=2.f*(x*z-w*y); R[7]=2.f*(y*z+w*x); R[8]=1.f-2.f*(x*x+y*y);
    }
}

// W1/W2 -> [n][k] fp16 hi + fp16 lo (lo = exact residual)
__global__ void precompute_W_kernel(const float* __restrict__ W1,
                                    const float* __restrict__ W2)
{
    const int idx = blockIdx.x*256 + threadIdx.x;   // 0..131071
    const int layer = idx >> 16;
    const int e = idx & 65535;
    const int k = e >> 8, n = e & 255;
    const float v = (layer ? W2 : W1)[k*HH + n];
    __half hi = __float2half_rn(v);
    __half lo = __float2half_rn(v - __half2float(hi));
    size_t o = ((size_t)(layer*2)*256 + n)*256 + k;       // [layer][0][n][k]
    *(__half*)(g_Wh + o*2)           = hi;
    *(__half*)(g_Wh + (o+65536)*2)   = lo;                // part stride 65536 elems
}

// ---------------- main kernel ----------------
// one k-chunk: 32 k x 256 n x 2 parts fp16 = 32KB; 256 threads x 8 x 16B
__device__ __forceinline__ void prefetch_chunk(uint32_t dst, int layer, int c, int t){
#pragma unroll
    for (int i = 0; i < 8; ++i) {
        const int idx = t*8 + i;                 // 0..2047
        const int p   = idx >> 10;
        const int n   = (idx >> 2) & 255;
        const int seg = idx & 3;
        const unsigned char* src = g_Wh + (size_t)layer*262144 + (size_t)p*131072
                                 + (size_t)n*512 + c*64 + seg*16;
        const uint32_t d = dst + p*20480 + n*(LDB*2) + seg*16;
        asm volatile("cp.async.cg.shared.global [%0], [%1], 16;" :: "r"(d), "l"(src));
    }
    asm volatile("cp.async.commit_group;" ::: "memory");
}

__device__ __forceinline__ void gemm_layer(int layer, int has_next, uint32_t sb,
    float acc[4][8][4], int t, int m0, int n0, int row_a, int k_a, int n_b, int k_b)
{
    for (int c = 0; c < 8; ++c) {
        const int g = layer*8 + c;
        if (c < 6)         prefetch_chunk(sb + WBUF_OFF + ((g+2)%3)*40960, layer,   c+2, t);
        else if (has_next) prefetch_chunk(sb + WBUF_OFF + ((g+2)%3)*40960, layer+1, c-6, t);
        if (has_next || c < 6) { asm volatile("cp.async.wait_group 2;" ::: "memory"); }
        else if (c == 6)       { asm volatile("cp.async.wait_group 1;" ::: "memory"); }
        else                   { asm volatile("cp.async.wait_group 0;" ::: "memory"); }
        __syncthreads();
        const uint32_t buf = sb + WBUF_OFF + (g%3)*40960;
#pragma unroll
        for (int ks = 0; ks < 2; ++ks) {
            uint32_t a[4][4];
#pragma unroll
            for (int mt = 0; mt < 4; ++mt) {
                const uint32_t ro = (uint32_t)((m0 + mt*16 + row_a)*LDA + c*32 + ks*16 + k_a)*2;
                ldsm4(a[mt], sb + A_OFF + ro);
            }
#pragma unroll
            for (int p = 0; p < 2; ++p) {
#pragma unroll
                for (int ng = 0; ng < 4; ++ng) {
                    uint32_t bb[4];
                    ldsm4(bb, buf + p*20480
                              + (uint32_t)((n0 + ng*16 + n_b)*LDB + ks*16 + k_b)*2);
#pragma unroll
                    for (int mt = 0; mt < 4; ++mt) {
                        mma16816(acc[mt][2*ng],   a[mt], bb[0], bb[1]);
                        mma16816(acc[mt][2*ng+1], a[mt], bb[2], bb[3]);
                    }
                }
            }
        }
        __syncthreads();
    }
}

__global__ void __launch_bounds__(256,1)
occ_mma_kernel(const float* __restrict__ ray_points,
               const float* __restrict__ translations,
               const float* __restrict__ scale,
               const float* __restrict__ Wp, const float* __restrict__ bp,
               const float* __restrict__ b1, const float* __restrict__ b2,
               const float* __restrict__ Wout, const float* __restrict__ bout,
               float* __restrict__ out)
{
    extern __shared__ __align__(16) unsigned char smem[];
    const uint32_t sb = smem_u32(smem);
    float* sWp  = (float*)(smem + WP_OFF);
    float* sbp  = (float*)(smem + BP_OFF);
    float* sb1  = (float*)(smem + B1_OFF);
    float* sb2  = (float*)(smem + B2_OFF);
    float* sWo  = (float*)(smem + WO_OFF);
    float* sXt  = (float*)(smem + XT_OFF);
    float* sFell= (float*)(smem + FELL_OFF);
    int*   sMi  = (int*)  (smem + MI_OFF);
    float* sP   = (float*)(smem + SP_OFF);

    const int t = threadIdx.x;
    const int w = t >> 5, l = t & 31;
    const int m0 = (w >> 2) * 64;           // 2 row groups x 64
    const int cg = w & 3;
    const int n0 = cg * 64;                 // 4 col groups x 64
    const int li = l & 7, grp = l >> 3;
    const int row_a = li + ((grp & 1) << 3);
    const int k_a   = (grp >> 1) << 3;
    const int n_b   = li + ((grp >> 1) << 3);
    const int k_b   = (grp & 1) << 3;

    const int item0 = blockIdx.x * TILE;
    const int b = item0 >> 17;

    prefetch_chunk(sb + WBUF_OFF,         0, 0, t);
    prefetch_chunk(sb + WBUF_OFF + 40960, 0, 1, t);

    sWp[t]=Wp[t]; sWp[256+t]=Wp[256+t]; sWp[512+t]=Wp[512+t];
    sbp[t]=bp[t]; sb1[t]=b1[t]; sb2[t]=b2[t]; sWo[t]=Wout[t];

    if (t < TILE) {
        const int item = item0 + t;
        const int rem = item & (NPTS*MM - 1);
        const int np_ = rem >> 4, m = rem & 15, bm = b*MM + m;
        const float px=ray_points[(b*NPTS+np_)*3], py=ray_points[(b*NPTS+np_)*3+1], pz=ray_points[(b*NPTS+np_)*3+2];
        const float cx=px-translations[bm*3], cy=py-translations[bm*3+1], cz=pz-translations[bm*3+2];
        const float* R = g_R + bm*9;
        const float x0=R[0]*cx+R[1]*cy+R[2]*cz;
        const float x1=R[3]*cx+R[4]*cy+R[5]*cz;
        const float x2=R[6]*cx+R[7]*cy+R[8]*cz;
        const float q0=x0/scale[bm*3], q1=x1/scale[bm*3+1], q2=x2/scale[bm*3+2];
        sXt[t*3]=x0; sXt[t*3+1]=x1; sXt[t*3+2]=x2;
        sFell[t]=q0*q0+q1*q1+q2*q2; sMi[t]=m;
    }
    __syncthreads();

    // Build A0 = relu(net0) as single fp16. Thread t: row r=t>>1, 128-col half (t&1).
    {
        const int r = t >> 1, hb = t & 1;
        const float x0=sXt[r*3], x1=sXt[r*3+1], x2=sXt[r*3+2];
        const float* cond = g_cond + (b*MM + sMi[r])*HH;
        uint32_t* dA = (uint32_t*)(smem + A_OFF + (r*LDA + hb*128)*2);
#pragma unroll 8
        for (int jj = 0; jj < 64; ++jj) {
            const int j = hb*128 + 2*jj;
            float v0 = fmaf(x0,sWp[j],  fmaf(x1,sWp[256+j],  fmaf(x2,sWp[512+j],  sbp[j]  +cond[j])));
            float v1 = fmaf(x0,sWp[j+1],fmaf(x1,sWp[256+j+1],fmaf(x2,sWp[512+j+1],sbp[j+1]+cond[j+1])));
            __half2 hp = __floats2half2_rn(fmaxf(v0,0.f), fmaxf(v1,0.f));
            dA[jj] = *reinterpret_cast<uint32_t*>(&hp);
        }
    }
    __syncthreads();

    float acc[4][8][4];
#pragma unroll
    for (int a=0;a<4;++a)
#pragma unroll
        for (int c=0;c<8;++c)
#pragma unroll
            for (int k=0;k<4;++k) acc[a][c][k]=0.f;

    // ---- GEMM1 ----
    gemm_layer(0, 1, sb, acc, t, m0, n0, row_a, k_a, n_b, k_b);

    // Epilogue1: A1 = relu(acc + b1) -> fp16 -> A smem
#pragma unroll
    for (int mt = 0; mt < 4; ++mt) {
#pragma unroll
        for (int nt = 0; nt < 8; ++nt) {
            const int j0 = n0 + nt*8 + ((l&3)<<1);
            const int r0 = m0 + mt*16 + (l>>2);
            __half2 hA = __floats2half2_rn(fmaxf(acc[mt][nt][0] + sb1[j0],   0.f),
                                           fmaxf(acc[mt][nt][1] + sb1[j0+1], 0.f));
            __half2 hB = __floats2half2_rn(fmaxf(acc[mt][nt][2] + sb1[j0],   0.f),
                                           fmaxf(acc[mt][nt][3] + sb1[j0+1], 0.f));
            *(uint32_t*)(smem + A_OFF + (r0*LDA + j0)*2)     = *reinterpret_cast<uint32_t*>(&hA);
            *(uint32_t*)(smem + A_OFF + ((r0+8)*LDA + j0)*2) = *reinterpret_cast<uint32_t*>(&hB);
            acc[mt][nt][0]=0.f; acc[mt][nt][1]=0.f; acc[mt][nt][2]=0.f; acc[mt][nt][3]=0.f;
        }
    }
    __syncthreads();

    // ---- GEMM2 ----
    gemm_layer(1, 0, sb, acc, t, m0, n0, row_a, k_a, n_b, k_b);

    // Final epilogue: net = net0 + acc + b2; p = sum relu(net)*Wout
    {
        float X0[4][2], X1[4][2], X2[4][2];
        int   Mi[4][2];
#pragma unroll
        for (int mt = 0; mt < 4; ++mt)
#pragma unroll
            for (int h = 0; h < 2; ++h) {
                const int r = m0 + mt*16 + (l>>2) + h*8;
                X0[mt][h]=sXt[r*3]; X1[mt][h]=sXt[r*3+1]; X2[mt][h]=sXt[r*3+2];
                Mi[mt][h]=sMi[r];
            }
        float ps[4][2];
#pragma unroll
        for (int mt = 0; mt < 4; ++mt) { ps[mt][0]=0.f; ps[mt][1]=0.f; }
#pragma unroll
        for (int mt = 0; mt < 4; ++mt) {
#pragma unroll
            for (int nt = 0; nt < 8; ++nt) {
                const int j0 = n0 + nt*8 + ((l&3)<<1);
#pragma unroll
                for (int k = 0; k < 4; ++k) {
                    const int j = j0 + (k & 1);
                    const int h = k >> 1;
                    const float cnd = g_cond[(b*MM + Mi[mt][h])*HH + j];
                    float net0 = fmaf(X0[mt][h],sWp[j],
                                 fmaf(X1[mt][h],sWp[256+j],
                                 fmaf(X2[mt][h],sWp[512+j], sbp[j] + cnd)));
                    float net = net0 + acc[mt][nt][k] + sb2[j];
                    ps[mt][h] = fmaf(fmaxf(net,0.f), sWo[j], ps[mt][h]);
                }
            }
        }
#pragma unroll
        for (int mt = 0; mt < 4; ++mt)
#pragma unroll
            for (int h = 0; h < 2; ++h) {
                float p = ps[mt][h];
                p += __shfl_xor_sync(0xffffffffu, p, 1);
                p += __shfl_xor_sync(0xffffffffu, p, 2);
                if ((l & 3) == 0) {
                    const int r = m0 + mt*16 + (l>>2) + h*8;
                    sP[r*4 + cg] = p;
                }
            }
    }
    __syncthreads();
    if (t < TILE) {
        const float occ = sP[t*4] + sP[t*4+1] + sP[t*4+2] + sP[t*4+3] + bout[0];
        const float F   = (sFell[t] <= 1.0f) ? occ : -100.0f;
        out[item0 + t]  = 1.0f / (1.0f + expf(-10.0f * F));
    }
}

// ---------------- launch ----------------
extern "C" void kernel_launch(void* const* d_in, const int* in_sizes, int n_in,
                              void* d_out, int out_size)
{
    const float* ray_points   = (const float*)d_in[0];
    const float* translations = (const float*)d_in[1];
    const float* rotations    = (const float*)d_in[2];
    const float* scale        = (const float*)d_in[3];
    const float* psf          = (const float*)d_in[4];
    const float* Wp   = (const float*)d_in[5];
    const float* bp   = (const float*)d_in[6];
    const float* Wc   = (const float*)d_in[7];
    const float* bc   = (const float*)d_in[8];
    const float* W1   = (const float*)d_in[9];
    const float* b1   = (const float*)d_in[10];
    const float* W2   = (const float*)d_in[11];
    const float* b2   = (const float*)d_in[12];
    const float* Wout = (const float*)d_in[13];
    const float* bout = (const float*)d_in[14];
    float*       out  = (float*)d_out;

    cudaFuncSetAttribute(occ_mma_kernel,
                         cudaFuncAttributeMaxDynamicSharedMemorySize, SMEM_BYTES);

    precompute_kernel<<<BD*MM, 256>>>(rotations, psf, Wc, bc);
    precompute_W_kernel<<<512, 256>>>(W1, W2);
    occ_mma_kernel<<<NBLK, 256, SMEM_BYTES>>>(ray_points, translations, scale,
                                              Wp, bp, b1, b2, Wout, bout, out);
}

// round 12
// speedup vs baseline: 1.5652x; 1.5652x over previous
#include <cuda_runtime.h>
#include <cuda_fp16.h>
#include <math.h>
#include <stdint.h>

#define BD 2
#define NPTS 8192
#define MM 16
#define HH 256
#define CC 128
#define ITEMS (BD*NPTS*MM)
#define TILE 128
#define NBLK (ITEMS/TILE)        // 2048
#define LDA 264                  // A smem row stride (fp16 elements)
#define LDB 40                   // W chunk row stride (fp16 elements)

// smem offsets (bytes)
#define A_OFF    0               // 128*264*2 = 67584
#define WBUF_OFF 67584           // 3 x 40960 = 122880
#define WP_OFF   190464          // 3*256*4
#define BP_OFF   193536
#define B1_OFF   194560
#define B2_OFF   195584
#define WO_OFF   196608
#define XT_OFF   197632          // 128*3*4
#define FELL_OFF 199168
#define MI_OFF   199680
#define SP_OFF   200192          // 128*4*4
#define SMEM_BYTES 202240

__device__ float g_cond[BD*MM*HH];   // [bm][j]
__device__ float g_R[BD*MM*9];
// W fp16: [layer][part(hi/lo)][n][k]; layer stride 262144B, part 131072B, n-row 512B
__device__ __align__(16) unsigned char g_Wh[2*2*256*256*2];

// ---------------- PTX helpers ----------------
__device__ __forceinline__ uint32_t smem_u32(const void* p){
    uint32_t a;
    asm("{ .reg .u64 t; cvta.to.shared.u64 t, %1; cvt.u32.u64 %0, t; }":"=r"(a):"l"(p));
    return a;
}
__device__ __forceinline__ void ldsm4(uint32_t* r, uint32_t addr){
    asm volatile("ldmatrix.sync.aligned.m8n8.x4.shared.b16 {%0,%1,%2,%3}, [%4];"
        : "=r"(r[0]),"=r"(r[1]),"=r"(r[2]),"=r"(r[3]) : "r"(addr));
}
__device__ __forceinline__ void mma16816(float* d, const uint32_t* a, uint32_t b0, uint32_t b1){
    asm volatile("mma.sync.aligned.m16n8k16.row.col.f32.f16.f16.f32 "
        "{%0,%1,%2,%3}, {%4,%5,%6,%7}, {%8,%9}, {%0,%1,%2,%3};"
        : "+f"(d[0]),"+f"(d[1]),"+f"(d[2]),"+f"(d[3])
        : "r"(a[0]),"r"(a[1]),"r"(a[2]),"r"(a[3]), "r"(b0),"r"(b1));
}

// ---------------- prologues ----------------
__global__ void precompute_kernel(const float* __restrict__ rotations,
                                  const float* __restrict__ psf,
                                  const float* __restrict__ Wc,
                                  const float* __restrict__ bc)
{
    __shared__ float s_psf[CC];
    const int bm = blockIdx.x, t = threadIdx.x;
    if (t < CC) s_psf[t] = psf[bm*CC + t];
    __syncthreads();
    float acc = bc[t];
#pragma unroll 8
    for (int k = 0; k < CC; ++k) acc = fmaf(s_psf[k], Wc[k*HH + t], acc);
    g_cond[bm*HH + t] = acc;
    if (t == 0) {
        float w=rotations[bm*4],x=rotations[bm*4+1],y=rotations[bm*4+2],z=rotations[bm*4+3];
        float inv = rsqrtf(w*w+x*x+y*y+z*z);
        w*=inv; x*=inv; y*=inv; z*=inv;
        float* R = g_R + bm*9;
        R[0]=1.f-2.f*(y*y+z*z); R[1]=2.f*(x*y-w*z); R[2]=2.f*(x*z+w*y);
        R[3]=2.f*(x*y+w*z); R[4]=1.f-2.f*(x*x+z*z); R[5]=2.f*(y*z-w*x);
        R[6]=2.f*(x*z-w*y); R[7]=2.f*(y*z+w*x); R[8]=1.f-2.f*(x*x+y*y);
    }
}

// W1/W2 -> [n][k] fp16 hi + fp16 lo (lo = residual)
__global__ void precompute_W_kernel(const float* __restrict__ W1,
                                    const float* __restrict__ W2)
{
    const int idx = blockIdx.x*256 + threadIdx.x;   // 0..131071
    const int layer = idx >> 16;
    const int e = idx & 65535;
    const int k = e >> 8, n = e & 255;
    const float v = (layer ? W2 : W1)[k*HH + n];
    __half hi = __float2half_rn(v);
    __half lo = __float2half_rn(v - __half2float(hi));
    size_t o = ((size_t)(layer*2)*256 + n)*256 + k;       // [layer][0][n][k]
    *(__half*)(g_Wh + o*2)           = hi;
    *(__half*)(g_Wh + (o+65536)*2)   = lo;                // part stride 65536 elems
}

// ---------------- main kernel ----------------
// one k-chunk: 32 k x 256 n x 2 parts fp16; 512 threads x 4 x 16B
__device__ __forceinline__ void prefetch_chunk(uint32_t dst, int layer, int c, int t){
#pragma unroll
    for (int i = 0; i < 4; ++i) {
        const int idx = t*4 + i;                 // 0..2047
        const int p   = idx >> 10;
        const int n   = (idx >> 2) & 255;
        const int seg = idx & 3;
        const unsigned char* src = g_Wh + (size_t)layer*262144 + (size_t)p*131072
                                 + (size_t)n*512 + c*64 + seg*16;
        const uint32_t d = dst + p*20480 + n*(LDB*2) + seg*16;
        asm volatile("cp.async.cg.shared.global [%0], [%1], 16;" :: "r"(d), "l"(src));
    }
    asm volatile("cp.async.commit_group;" ::: "memory");
}

__device__ __forceinline__ void gemm_layer(int layer, int has_next, uint32_t sb,
    float acc[2][8][4], int t, int m0, int n0, int row_a, int k_a, int n_b, int k_b)
{
    for (int c = 0; c < 8; ++c) {
        const int g = layer*8 + c;
        if (c < 6)         prefetch_chunk(sb + WBUF_OFF + ((g+2)%3)*40960, layer,   c+2, t);
        else if (has_next) prefetch_chunk(sb + WBUF_OFF + ((g+2)%3)*40960, layer+1, c-6, t);
        if (has_next || c < 6) { asm volatile("cp.async.wait_group 2;" ::: "memory"); }
        else if (c == 6)       { asm volatile("cp.async.wait_group 1;" ::: "memory"); }
        else                   { asm volatile("cp.async.wait_group 0;" ::: "memory"); }
        __syncthreads();
        const uint32_t buf = sb + WBUF_OFF + (g%3)*40960;
#pragma unroll
        for (int ks = 0; ks < 2; ++ks) {
            uint32_t a[2][4];
#pragma unroll
            for (int mt = 0; mt < 2; ++mt) {
                const uint32_t ro = (uint32_t)((m0 + mt*16 + row_a)*LDA + c*32 + ks*16 + k_a)*2;
                ldsm4(a[mt], sb + A_OFF + ro);
            }
#pragma unroll
            for (int p = 0; p < 2; ++p) {
#pragma unroll
                for (int ng = 0; ng < 4; ++ng) {
                    uint32_t bb[4];
                    ldsm4(bb, buf + p*20480
                              + (uint32_t)((n0 + ng*16 + n_b)*LDB + ks*16 + k_b)*2);
#pragma unroll
                    for (int mt = 0; mt < 2; ++mt) {
                        mma16816(acc[mt][2*ng],   a[mt], bb[0], bb[1]);
                        mma16816(acc[mt][2*ng+1], a[mt], bb[2], bb[3]);
                    }
                }
            }
        }
        __syncthreads();
    }
}

__global__ void __launch_bounds__(512,1)
occ_mma_kernel(const float* __restrict__ ray_points,
               const float* __restrict__ translations,
               const float* __restrict__ scale,
               const float* __restrict__ Wp, const float* __restrict__ bp,
               const float* __restrict__ b1, const float* __restrict__ b2,
               const float* __restrict__ Wout, const float* __restrict__ bout,
               float* __restrict__ out)
{
    extern __shared__ __align__(16) unsigned char smem[];
    const uint32_t sb = smem_u32(smem);
    float* sWp  = (float*)(smem + WP_OFF);
    float* sbp  = (float*)(smem + BP_OFF);
    float* sb1  = (float*)(smem + B1_OFF);
    float* sb2  = (float*)(smem + B2_OFF);
    float* sWo  = (float*)(smem + WO_OFF);
    float* sXt  = (float*)(smem + XT_OFF);
    float* sFell= (float*)(smem + FELL_OFF);
    int*   sMi  = (int*)  (smem + MI_OFF);
    float* sP   = (float*)(smem + SP_OFF);

    const int t = threadIdx.x;
    const int w = t >> 5, l = t & 31;
    const int m0 = (w >> 2) * 32;           // 4 row groups x 32
    const int cg = w & 3;
    const int n0 = cg * 64;                 // 4 col groups x 64
    const int li = l & 7, grp = l >> 3;
    const int row_a = li + ((grp & 1) << 3);
    const int k_a   = (grp >> 1) << 3;
    const int n_b   = li + ((grp >> 1) << 3);
    const int k_b   = (grp & 1) << 3;

    const int item0 = blockIdx.x * TILE;
    const int b = item0 >> 17;

    prefetch_chunk(sb + WBUF_OFF,         0, 0, t);
    prefetch_chunk(sb + WBUF_OFF + 40960, 0, 1, t);

    if (t < 256) {
        sWp[t]=Wp[t]; sWp[256+t]=Wp[256+t]; sWp[512+t]=Wp[512+t];
        sbp[t]=bp[t]; sb1[t]=b1[t]; sb2[t]=b2[t]; sWo[t]=Wout[t];
    }
    if (t < TILE) {
        const int item = item0 + t;
        const int rem = item & (NPTS*MM - 1);
        const int np_ = rem >> 4, m = rem & 15, bm = b*MM + m;
        const float px=ray_points[(b*NPTS+np_)*3], py=ray_points[(b*NPTS+np_)*3+1], pz=ray_points[(b*NPTS+np_)*3+2];
        const float cx=px-translations[bm*3], cy=py-translations[bm*3+1], cz=pz-translations[bm*3+2];
        const float* R = g_R + bm*9;
        const float x0=R[0]*cx+R[1]*cy+R[2]*cz;
        const float x1=R[3]*cx+R[4]*cy+R[5]*cz;
        const float x2=R[6]*cx+R[7]*cy+R[8]*cz;
        const float q0=x0/scale[bm*3], q1=x1/scale[bm*3+1], q2=x2/scale[bm*3+2];
        sXt[t*3]=x0; sXt[t*3+1]=x1; sXt[t*3+2]=x2;
        sFell[t]=q0*q0+q1*q1+q2*q2; sMi[t]=m;
    }
    __syncthreads();

    // Build A0 = relu(net0) as fp16. Thread t: row r=t>>2, quarter q=t&3 (64 cols).
    {
        const int r = t >> 2, q = t & 3;
        const float x0=sXt[r*3], x1=sXt[r*3+1], x2=sXt[r*3+2];
        const float* cond = g_cond + (b*MM + sMi[r])*HH;
        uint32_t* dA = (uint32_t*)(smem + A_OFF + (r*LDA + q*64)*2);
#pragma unroll 8
        for (int jj = 0; jj < 32; ++jj) {
            const int j = q*64 + 2*jj;
            float v0 = fmaf(x0,sWp[j],  fmaf(x1,sWp[256+j],  fmaf(x2,sWp[512+j],  sbp[j]  +cond[j])));
            float v1 = fmaf(x0,sWp[j+1],fmaf(x1,sWp[256+j+1],fmaf(x2,sWp[512+j+1],sbp[j+1]+cond[j+1])));
            __half2 hp = __floats2half2_rn(fmaxf(v0,0.f), fmaxf(v1,0.f));
            dA[jj] = *reinterpret_cast<uint32_t*>(&hp);
        }
    }
    __syncthreads();

    float acc[2][8][4];
#pragma unroll
    for (int a=0;a<2;++a)
#pragma unroll
        for (int c=0;c<8;++c)
#pragma unroll
            for (int k=0;k<4;++k) acc[a][c][k]=0.f;

    // ---- GEMM1 ----
    gemm_layer(0, 1, sb, acc, t, m0, n0, row_a, k_a, n_b, k_b);

    // Epilogue1: A1 = relu(acc + b1) -> fp16 -> A smem
#pragma unroll
    for (int mt = 0; mt < 2; ++mt) {
#pragma unroll
        for (int nt = 0; nt < 8; ++nt) {
            const int j0 = n0 + nt*8 + ((l&3)<<1);
            const int r0 = m0 + mt*16 + (l>>2);
            __half2 hA = __floats2half2_rn(fmaxf(acc[mt][nt][0] + sb1[j0],   0.f),
                                           fmaxf(acc[mt][nt][1] + sb1[j0+1], 0.f));
            __half2 hB = __floats2half2_rn(fmaxf(acc[mt][nt][2] + sb1[j0],   0.f),
                                           fmaxf(acc[mt][nt][3] + sb1[j0+1], 0.f));
            *(uint32_t*)(smem + A_OFF + (r0*LDA + j0)*2)     = *reinterpret_cast<uint32_t*>(&hA);
            *(uint32_t*)(smem + A_OFF + ((r0+8)*LDA + j0)*2) = *reinterpret_cast<uint32_t*>(&hB);
            acc[mt][nt][0]=0.f; acc[mt][nt][1]=0.f; acc[mt][nt][2]=0.f; acc[mt][nt][3]=0.f;
        }
    }
    __syncthreads();

    // ---- GEMM2 ----
    gemm_layer(1, 0, sb, acc, t, m0, n0, row_a, k_a, n_b, k_b);

    // Final epilogue: net = net0 + acc + b2; p = sum relu(net)*Wout
    {
        float X0[2][2], X1[2][2], X2[2][2];
        int   Mi[2][2];
#pragma unroll
        for (int mt = 0; mt < 2; ++mt)
#pragma unroll
            for (int h = 0; h < 2; ++h) {
                const int r = m0 + mt*16 + (l>>2) + h*8;
                X0[mt][h]=sXt[r*3]; X1[mt][h]=sXt[r*3+1]; X2[mt][h]=sXt[r*3+2];
                Mi[mt][h]=sMi[r];
            }
        float ps[2][2] = {{0.f,0.f},{0.f,0.f}};
#pragma unroll
        for (int mt = 0; mt < 2; ++mt) {
#pragma unroll
            for (int nt = 0; nt < 8; ++nt) {
                const int j0 = n0 + nt*8 + ((l&3)<<1);
#pragma unroll
                for (int k = 0; k < 4; ++k) {
                    const int j = j0 + (k & 1);
                    const int h = k >> 1;
                    const float cnd = g_cond[(b*MM + Mi[mt][h])*HH + j];
                    float net0 = fmaf(X0[mt][h],sWp[j],
                                 fmaf(X1[mt][h],sWp[256+j],
                                 fmaf(X2[mt][h],sWp[512+j], sbp[j] + cnd)));
                    float net = net0 + acc[mt][nt][k] + sb2[j];
                    ps[mt][h] = fmaf(fmaxf(net,0.f), sWo[j], ps[mt][h]);
                }
            }
        }
#pragma unroll
        for (int mt = 0; mt < 2; ++mt)
#pragma unroll
            for (int h = 0; h < 2; ++h) {
                float p = ps[mt][h];
                p += __shfl_xor_sync(0xffffffffu, p, 1);
                p += __shfl_xor_sync(0xffffffffu, p, 2);
                if ((l & 3) == 0) {
                    const int r = m0 + mt*16 + (l>>2) + h*8;
                    sP[r*4 + cg] = p;
                }
            }
    }
    __syncthreads();
    if (t < TILE) {
        const float occ = sP[t*4] + sP[t*4+1] + sP[t*4+2] + sP[t*4+3] + bout[0];
        const float F   = (sFell[t] <= 1.0f) ? occ : -100.0f;
        out[item0 + t]  = 1.0f / (1.0f + expf(-10.0f * F));
    }
}

// ---------------- launch ----------------
extern "C" void kernel_launch(void* const* d_in, const int* in_sizes, int n_in,
                              void* d_out, int out_size)
{
    const float* ray_points   = (const float*)d_in[0];
    const float* translations = (const float*)d_in[1];
    const float* rotations    = (const float*)d_in[2];
    const float* scale        = (const float*)d_in[3];
    const float* psf          = (const float*)d_in[4];
    const float* Wp   = (const float*)d_in[5];
    const float* bp   = (const float*)d_in[6];
    const float* Wc   = (const float*)d_in[7];
    const float* bc   = (const float*)d_in[8];
    const float* W1   = (const float*)d_in[9];
    const float* b1   = (const float*)d_in[10];
    const float* W2   = (const float*)d_in[11];
    const float* b2   = (const float*)d_in[12];
    const float* Wout = (const float*)d_in[13];
    const float* bout = (const float*)d_in[14];
    float*       out  = (float*)d_out;

    cudaFuncSetAttribute(occ_mma_kernel,
                         cudaFuncAttributeMaxDynamicSharedMemorySize, SMEM_BYTES);

    precompute_kernel<<<BD*MM, 256>>>(rotations, psf, Wc, bc);
    precompute_W_kernel<<<512, 256>>>(W1, W2);
    occ_mma_kernel<<<NBLK, 512, SMEM_BYTES>>>(ray_points, translations, scale,
                                              Wp, bp, b1, b2, Wout, bout, out);
}

// round 13
// speedup vs baseline: 1.8918x; 1.2087x over previous
#include <cuda_runtime.h>
#include <cuda_fp16.h>
#include <math.h>
#include <stdint.h>

#define BD 2
#define NPTS 8192
#define MM 16
#define HH 256
#define CC 128
#define ITEMS (BD*NPTS*MM)
#define TILE 64
#define NBLK (ITEMS/TILE)        // 4096
#define LDA 264                  // A smem row stride (fp16 elements)
#define LDB 40                   // W chunk row stride (fp16 elements)
#define WCH 20480                // one weight chunk buffer (256 rows x 80B)

// smem offsets (bytes)
#define A_OFF    0               // 64*264*2 = 33792
#define WBUF_OFF 33792           // 3 x 20480 = 61440
#define WP_OFF   95232           // 3*256*4
#define BP_OFF   98304
#define B1_OFF   99328
#define B2_OFF   100352
#define WO_OFF   101376
#define XT_OFF   102400          // 64*3*4
#define FELL_OFF 103168
#define MI_OFF   103424
#define SP_OFF   103680          // 64*4*4
#define SMEM_BYTES 104704

__device__ float g_cond[BD*MM*HH];   // [bm][j]
__device__ float g_R[BD*MM*9];
// W fp16 (hi only): [layer][n][k]; layer stride 131072B, n-row 512B
__device__ __align__(16) unsigned char g_Wh[2*256*256*2];

// ---------------- PTX helpers ----------------
__device__ __forceinline__ uint32_t smem_u32(const void* p){
    uint32_t a;
    asm("{ .reg .u64 t; cvta.to.shared.u64 t, %1; cvt.u32.u64 %0, t; }":"=r"(a):"l"(p));
    return a;
}
__device__ __forceinline__ void ldsm4(uint32_t* r, uint32_t addr){
    asm volatile("ldmatrix.sync.aligned.m8n8.x4.shared.b16 {%0,%1,%2,%3}, [%4];"
        : "=r"(r[0]),"=r"(r[1]),"=r"(r[2]),"=r"(r[3]) : "r"(addr));
}
__device__ __forceinline__ void mma16816(float* d, const uint32_t* a, uint32_t b0, uint32_t b1){
    asm volatile("mma.sync.aligned.m16n8k16.row.col.f32.f16.f16.f32 "
        "{%0,%1,%2,%3}, {%4,%5,%6,%7}, {%8,%9}, {%0,%1,%2,%3};"
        : "+f"(d[0]),"+f"(d[1]),"+f"(d[2]),"+f"(d[3])
        : "r"(a[0]),"r"(a[1]),"r"(a[2]),"r"(a[3]), "r"(b0),"r"(b1));
}

// ---------------- prologues ----------------
__global__ void precompute_kernel(const float* __restrict__ rotations,
                                  const float* __restrict__ psf,
                                  const float* __restrict__ Wc,
                                  const float* __restrict__ bc)
{
    __shared__ float s_psf[CC];
    const int bm = blockIdx.x, t = threadIdx.x;
    if (t < CC) s_psf[t] = psf[bm*CC + t];
    __syncthreads();
    float acc = bc[t];
#pragma unroll 8
    for (int k = 0; k < CC; ++k) acc = fmaf(s_psf[k], Wc[k*HH + t], acc);
    g_cond[bm*HH + t] = acc;
    if (t == 0) {
        float w=rotations[bm*4],x=rotations[bm*4+1],y=rotations[bm*4+2],z=rotations[bm*4+3];
        float inv = rsqrtf(w*w+x*x+y*y+z*z);
        w*=inv; x*=inv; y*=inv; z*=inv;
        float* R = g_R + bm*9;
        R[0]=1.f-2.f*(y*y+z*z); R[1]=2.f*(x*y-w*z); R[2]=2.f*(x*z+w*y);
        R[3]=2.f*(x*y+w*z); R[4]=1.f-2.f*(x*x+z*z); R[5]=2.f*(y*z-w*x);
        R[6]=2.f*(x*z-w*y); R[7]=2.f*(y*z+w*x); R[8]=1.f-2.f*(x*x+y*y);
    }
}

// W1/W2 -> [n][k] fp16
__global__ void precompute_W_kernel(const float* __restrict__ W1,
                                    const float* __restrict__ W2)
{
    const int idx = blockIdx.x*256 + threadIdx.x;   // 0..131071
    const int layer = idx >> 16;
    const int e = idx & 65535;
    const int k = e >> 8, n = e & 255;
    const float v = (layer ? W2 : W1)[k*HH + n];
    size_t o = ((size_t)layer*256 + n)*256 + k;
    *(__half*)(g_Wh + o*2) = __float2half_rn(v);
}

// ---------------- main kernel ----------------
// one k-chunk: 32 k x 256 n fp16 = 16KB; 256 threads x 4 x 16B
__device__ __forceinline__ void prefetch_chunk(uint32_t dst, int layer, int c, int t){
#pragma unroll
    for (int i = 0; i < 4; ++i) {
        const int idx = t*4 + i;                 // 0..1023
        const int n   = idx >> 2;
        const int seg = idx & 3;
        const unsigned char* src = g_Wh + (size_t)layer*131072
                                 + (size_t)n*512 + c*64 + seg*16;
        const uint32_t d = dst + n*(LDB*2) + seg*16;
        asm volatile("cp.async.cg.shared.global [%0], [%1], 16;" :: "r"(d), "l"(src));
    }
    asm volatile("cp.async.commit_group;" ::: "memory");
}

__device__ __forceinline__ void gemm_layer(int layer, int has_next, uint32_t sb,
    float acc[2][8][4], int t, int m0, int n0, int row_a, int k_a, int n_b, int k_b)
{
    for (int c = 0; c < 8; ++c) {
        const int g = layer*8 + c;
        if (c < 6)         prefetch_chunk(sb + WBUF_OFF + ((g+2)%3)*WCH, layer,   c+2, t);
        else if (has_next) prefetch_chunk(sb + WBUF_OFF + ((g+2)%3)*WCH, layer+1, c-6, t);
        if (has_next || c < 6) { asm volatile("cp.async.wait_group 2;" ::: "memory"); }
        else if (c == 6)       { asm volatile("cp.async.wait_group 1;" ::: "memory"); }
        else                   { asm volatile("cp.async.wait_group 0;" ::: "memory"); }
        __syncthreads();
        const uint32_t buf = sb + WBUF_OFF + (g%3)*WCH;
#pragma unroll
        for (int ks = 0; ks < 2; ++ks) {
            uint32_t a[2][4];
#pragma unroll
            for (int mt = 0; mt < 2; ++mt) {
                const uint32_t ro = (uint32_t)((m0 + mt*16 + row_a)*LDA + c*32 + ks*16 + k_a)*2;
                ldsm4(a[mt], sb + A_OFF + ro);
            }
#pragma unroll
            for (int ng = 0; ng < 4; ++ng) {
                uint32_t bb[4];
                ldsm4(bb, buf + (uint32_t)((n0 + ng*16 + n_b)*LDB + ks*16 + k_b)*2);
#pragma unroll
                for (int mt = 0; mt < 2; ++mt) {
                    mma16816(acc[mt][2*ng],   a[mt], bb[0], bb[1]);
                    mma16816(acc[mt][2*ng+1], a[mt], bb[2], bb[3]);
                }
            }
        }
        __syncthreads();
    }
}

__global__ void __launch_bounds__(256,2)
occ_mma_kernel(const float* __restrict__ ray_points,
               const float* __restrict__ translations,
               const float* __restrict__ scale,
               const float* __restrict__ Wp, const float* __restrict__ bp,
               const float* __restrict__ b1, const float* __restrict__ b2,
               const float* __restrict__ Wout, const float* __restrict__ bout,
               float* __restrict__ out)
{
    extern __shared__ __align__(16) unsigned char smem[];
    const uint32_t sb = smem_u32(smem);
    float* sWp  = (float*)(smem + WP_OFF);
    float* sbp  = (float*)(smem + BP_OFF);
    float* sb1  = (float*)(smem + B1_OFF);
    float* sb2  = (float*)(smem + B2_OFF);
    float* sWo  = (float*)(smem + WO_OFF);
    float* sXt  = (float*)(smem + XT_OFF);
    float* sFell= (float*)(smem + FELL_OFF);
    int*   sMi  = (int*)  (smem + MI_OFF);
    float* sP   = (float*)(smem + SP_OFF);

    const int t = threadIdx.x;
    const int w = t >> 5, l = t & 31;
    const int m0 = (w >> 2) * 32;           // 2 row groups x 32
    const int cg = w & 3;
    const int n0 = cg * 64;                 // 4 col groups x 64
    const int li = l & 7, grp = l >> 3;
    const int row_a = li + ((grp & 1) << 3);
    const int k_a   = (grp >> 1) << 3;
    const int n_b   = li + ((grp >> 1) << 3);
    const int k_b   = (grp & 1) << 3;

    const int item0 = blockIdx.x * TILE;
    const int b = item0 >> 17;

    prefetch_chunk(sb + WBUF_OFF,       0, 0, t);
    prefetch_chunk(sb + WBUF_OFF + WCH, 0, 1, t);

    sWp[t]=Wp[t]; sWp[256+t]=Wp[256+t]; sWp[512+t]=Wp[512+t];
    sbp[t]=bp[t]; sb1[t]=b1[t]; sb2[t]=b2[t]; sWo[t]=Wout[t];

    if (t < TILE) {
        const int item = item0 + t;
        const int rem = item & (NPTS*MM - 1);
        const int np_ = rem >> 4, m = rem & 15, bm = b*MM + m;
        const float px=ray_points[(b*NPTS+np_)*3], py=ray_points[(b*NPTS+np_)*3+1], pz=ray_points[(b*NPTS+np_)*3+2];
        const float cx=px-translations[bm*3], cy=py-translations[bm*3+1], cz=pz-translations[bm*3+2];
        const float* R = g_R + bm*9;
        const float x0=R[0]*cx+R[1]*cy+R[2]*cz;
        const float x1=R[3]*cx+R[4]*cy+R[5]*cz;
        const float x2=R[6]*cx+R[7]*cy+R[8]*cz;
        const float q0=x0/scale[bm*3], q1=x1/scale[bm*3+1], q2=x2/scale[bm*3+2];
        sXt[t*3]=x0; sXt[t*3+1]=x1; sXt[t*3+2]=x2;
        sFell[t]=q0*q0+q1*q1+q2*q2; sMi[t]=m;
    }
    __syncthreads();

    // Build A0 = relu(net0) as fp16. Thread t: row r=t>>2, quarter q=t&3 (64 cols).
    {
        const int r = t >> 2, q = t & 3;
        const float x0=sXt[r*3], x1=sXt[r*3+1], x2=sXt[r*3+2];
        const float* cond = g_cond + (b*MM + sMi[r])*HH;
        uint32_t* dA = (uint32_t*)(smem + A_OFF + (r*LDA + q*64)*2);
#pragma unroll 8
        for (int jj = 0; jj < 32; ++jj) {
            const int j = q*64 + 2*jj;
            float v0 = fmaf(x0,sWp[j],  fmaf(x1,sWp[256+j],  fmaf(x2,sWp[512+j],  sbp[j]  +cond[j])));
            float v1 = fmaf(x0,sWp[j+1],fmaf(x1,sWp[256+j+1],fmaf(x2,sWp[512+j+1],sbp[j+1]+cond[j+1])));
            __half2 hp = __floats2half2_rn(fmaxf(v0,0.f), fmaxf(v1,0.f));
            dA[jj] = *reinterpret_cast<uint32_t*>(&hp);
        }
    }
    __syncthreads();

    float acc[2][8][4];
#pragma unroll
    for (int a=0;a<2;++a)
#pragma unroll
        for (int c=0;c<8;++c)
#pragma unroll
            for (int k=0;k<4;++k) acc[a][c][k]=0.f;

    // ---- GEMM1 ----
    gemm_layer(0, 1, sb, acc, t, m0, n0, row_a, k_a, n_b, k_b);

    // Epilogue1: A1 = relu(acc + b1) -> fp16 -> A smem
#pragma unroll
    for (int mt = 0; mt < 2; ++mt) {
#pragma unroll
        for (int nt = 0; nt < 8; ++nt) {
            const int j0 = n0 + nt*8 + ((l&3)<<1);
            const int r0 = m0 + mt*16 + (l>>2);
            __half2 hA = __floats2half2_rn(fmaxf(acc[mt][nt][0] + sb1[j0],   0.f),
                                           fmaxf(acc[mt][nt][1] + sb1[j0+1], 0.f));
            __half2 hB = __floats2half2_rn(fmaxf(acc[mt][nt][2] + sb1[j0],   0.f),
                                           fmaxf(acc[mt][nt][3] + sb1[j0+1], 0.f));
            *(uint32_t*)(smem + A_OFF + (r0*LDA + j0)*2)     = *reinterpret_cast<uint32_t*>(&hA);
            *(uint32_t*)(smem + A_OFF + ((r0+8)*LDA + j0)*2) = *reinterpret_cast<uint32_t*>(&hB);
            acc[mt][nt][0]=0.f; acc[mt][nt][1]=0.f; acc[mt][nt][2]=0.f; acc[mt][nt][3]=0.f;
        }
    }
    __syncthreads();

    // ---- GEMM2 ----
    gemm_layer(1, 0, sb, acc, t, m0, n0, row_a, k_a, n_b, k_b);

    // Final epilogue: net = net0 + acc + b2; p = sum relu(net)*Wout
    {
        float X0[2][2], X1[2][2], X2[2][2];
        int   Mi[2][2];
#pragma unroll
        for (int mt = 0; mt < 2; ++mt)
#pragma unroll
            for (int h = 0; h < 2; ++h) {
                const int r = m0 + mt*16 + (l>>2) + h*8;
                X0[mt][h]=sXt[r*3]; X1[mt][h]=sXt[r*3+1]; X2[mt][h]=sXt[r*3+2];
                Mi[mt][h]=sMi[r];
            }
        float ps[2][2] = {{0.f,0.f},{0.f,0.f}};
#pragma unroll
        for (int mt = 0; mt < 2; ++mt) {
#pragma unroll
            for (int nt = 0; nt < 8; ++nt) {
                const int j0 = n0 + nt*8 + ((l&3)<<1);
#pragma unroll
                for (int k = 0; k < 4; ++k) {
                    const int j = j0 + (k & 1);
                    const int h = k >> 1;
                    const float cnd = g_cond[(b*MM + Mi[mt][h])*HH + j];
                    float net0 = fmaf(X0[mt][h],sWp[j],
                                 fmaf(X1[mt][h],sWp[256+j],
                                 fmaf(X2[mt][h],sWp[512+j], sbp[j] + cnd)));
                    float net = net0 + acc[mt][nt][k] + sb2[j];
                    ps[mt][h] = fmaf(fmaxf(net,0.f), sWo[j], ps[mt][h]);
                }
            }
        }
#pragma unroll
        for (int mt = 0; mt < 2; ++mt)
#pragma unroll
            for (int h = 0; h < 2; ++h) {
                float p = ps[mt][h];
                p += __shfl_xor_sync(0xffffffffu, p, 1);
                p += __shfl_xor_sync(0xffffffffu, p, 2);
                if ((l & 3) == 0) {
                    const int r = m0 + mt*16 + (l>>2) + h*8;
                    sP[r*4 + cg] = p;
                }
            }
    }
    __syncthreads();
    if (t < TILE) {
        const float occ = sP[t*4] + sP[t*4+1] + sP[t*4+2] + sP[t*4+3] + bout[0];
        const float F   = (sFell[t] <= 1.0f) ? occ : -100.0f;
        out[item0 + t]  = 1.0f / (1.0f + expf(-10.0f * F));
    }
}

// ---------------- launch ----------------
extern "C" void kernel_launch(void* const* d_in, const int* in_sizes, int n_in,
                              void* d_out, int out_size)
{
    const float* ray_points   = (const float*)d_in[0];
    const float* translations = (const float*)d_in[1];
    const float* rotations    = (const float*)d_in[2];
    const float* scale        = (const float*)d_in[3];
    const float* psf          = (const float*)d_in[4];
    const float* Wp   = (const float*)d_in[5];
    const float* bp   = (const float*)d_in[6];
    const float* Wc   = (const float*)d_in[7];
    const float* bc   = (const float*)d_in[8];
    const float* W1   = (const float*)d_in[9];
    const float* b1   = (const float*)d_in[10];
    const float* W2   = (const float*)d_in[11];
    const float* b2   = (const float*)d_in[12];
    const float* Wout = (const float*)d_in[13];
    const float* bout = (const float*)d_in[14];
    float*       out  = (float*)d_out;

    cudaFuncSetAttribute(occ_mma_kernel,
                         cudaFuncAttributeMaxDynamicSharedMemorySize, SMEM_BYTES);

    precompute_kernel<<<BD*MM, 256>>>(rotations, psf, Wc, bc);
    precompute_W_kernel<<<512, 256>>>(W1, W2);
    occ_mma_kernel<<<NBLK, 256, SMEM_BYTES>>>(ray_points, translations, scale,
                                              Wp, bp, b1, b2, Wout, bout, out);
}

// round 16
// speedup vs baseline: 2.8237x; 1.4925x over previous
#include <cuda_runtime.h>
#include <cuda_fp16.h>
#include <math.h>
#include <stdint.h>

#define BD 2
#define NPTS 8192
#define MM 16
#define HH 256
#define CC 128
#define ITEMS (BD*NPTS*MM)
#define TILE 64
#define NBLK (ITEMS/TILE)        // 4096
#define LDA 264                  // A smem row stride (fp16 elements)
#define LDB 40                   // W chunk row stride (fp16 elements)
#define WCH 20480                // one weight chunk buffer (256 rows x 80B)
#define LDC 264                  // sCond row stride (fp32 words)

// smem offsets (bytes)
#define A_OFF    0               // 64*264*2 = 33792
#define WBUF_OFF 33792           // 2 x 20480 = 40960
#define COND_OFF 74752           // 16*264*4 = 16896
#define WP_OFF   91648           // 3*256*4
#define BP_OFF   94720
#define B1_OFF   95744
#define B2_OFF   96768
#define WO_OFF   97792
#define XT_OFF   98816           // 64*3*4
#define FELL_OFF 99584
#define MI_OFF   99840
#define SP_OFF   100096          // 64*4*4
#define SMEM_BYTES 101120

__device__ float g_cond[BD*MM*HH];   // [bm][j]
__device__ float g_R[BD*MM*9];
// W fp16: [layer][n][k]; layer stride 131072B, n-row 512B
__device__ __align__(16) unsigned char g_Wh[2*256*256*2];

// ---------------- PTX helpers ----------------
__device__ __forceinline__ uint32_t smem_u32(const void* p){
    uint32_t a;
    asm("{ .reg .u64 t; cvta.to.shared.u64 t, %1; cvt.u32.u64 %0, t; }":"=r"(a):"l"(p));
    return a;
}
__device__ __forceinline__ void ldsm4(uint32_t* r, uint32_t addr){
    asm volatile("ldmatrix.sync.aligned.m8n8.x4.shared.b16 {%0,%1,%2,%3}, [%4];"
        : "=r"(r[0]),"=r"(r[1]),"=r"(r[2]),"=r"(r[3]) : "r"(addr));
}
__device__ __forceinline__ void mma16816(float* d, const uint32_t* a, uint32_t b0, uint32_t b1){
    asm volatile("mma.sync.aligned.m16n8k16.row.col.f32.f16.f16.f32 "
        "{%0,%1,%2,%3}, {%4,%5,%6,%7}, {%8,%9}, {%0,%1,%2,%3};"
        : "+f"(d[0]),"+f"(d[1]),"+f"(d[2]),"+f"(d[3])
        : "r"(a[0]),"r"(a[1]),"r"(a[2]),"r"(a[3]), "r"(b0),"r"(b1));
}

// ---------------- merged prologue ----------------
// blocks 0..31: cond + rotation. blocks 32..543: W1/W2 -> [n][k] fp16.
__global__ void prologue_kernel(const float* __restrict__ rotations,
                                const float* __restrict__ psf,
                                const float* __restrict__ Wc,
                                const float* __restrict__ bc,
                                const float* __restrict__ W1,
                                const float* __restrict__ W2)
{
    const int t = threadIdx.x;
    if (blockIdx.x < 32) {
        __shared__ float s_psf[CC];
        const int bm = blockIdx.x;
        if (t < CC) s_psf[t] = psf[bm*CC + t];
        __syncthreads();
        float acc = bc[t];
#pragma unroll 8
        for (int k = 0; k < CC; ++k) acc = fmaf(s_psf[k], Wc[k*HH + t], acc);
        g_cond[bm*HH + t] = acc;
        if (t == 0) {
            float w=rotations[bm*4],x=rotations[bm*4+1],y=rotations[bm*4+2],z=rotations[bm*4+3];
            float inv = rsqrtf(w*w+x*x+y*y+z*z);
            w*=inv; x*=inv; y*=inv; z*=inv;
            float* R = g_R + bm*9;
            R[0]=1.f-2.f*(y*y+z*z); R[1]=2.f*(x*y-w*z); R[2]=2.f*(x*z+w*y);
            R[3]=2.f*(x*y+w*z); R[4]=1.f-2.f*(x*x+z*z); R[5]=2.f*(y*z-w*x);
            R[6]=2.f*(x*z-w*y); R[7]=2.f*(y*z+w*x); R[8]=1.f-2.f*(x*x+y*y);
        }
    } else {
        const int idx = (blockIdx.x - 32)*256 + t;   // 0..131071
        const int layer = idx >> 16;
        const int e = idx & 65535;
        const int k = e >> 8, n = e & 255;
        const float v = (layer ? W2 : W1)[k*HH + n];
        size_t o = ((size_t)layer*256 + n)*256 + k;
        *(__half*)(g_Wh + o*2) = __float2half_rn(v);
    }
}

// ---------------- main kernel ----------------
// one k-chunk: 32 k x 256 n fp16 = 16KB; 256 threads x 4 x 16B
__device__ __forceinline__ void prefetch_chunk(uint32_t dst, int layer, int c, int t){
#pragma unroll
    for (int i = 0; i < 4; ++i) {
        const int idx = t*4 + i;                 // 0..1023
        const int n   = idx >> 2;
        const int seg = idx & 3;
        const unsigned char* src = g_Wh + (size_t)layer*131072
                                 + (size_t)n*512 + c*64 + seg*16;
        const uint32_t d = dst + n*(LDB*2) + seg*16;
        asm volatile("cp.async.cg.shared.global [%0], [%1], 16;" :: "r"(d), "l"(src));
    }
    asm volatile("cp.async.commit_group;" ::: "memory");
}

__device__ __forceinline__ void gemm_layer(int layer, int has_next, uint32_t sb,
    float acc[2][8][4], int t, int m0, int n0, int row_a, int k_a, int n_b, int k_b)
{
    for (int c = 0; c < 8; ++c) {
        if (c < 7)         prefetch_chunk(sb + WBUF_OFF + ((c+1)&1)*WCH, layer,   c+1, t);
        else if (has_next) prefetch_chunk(sb + WBUF_OFF + ((c+1)&1)*WCH, layer+1, 0,   t);
        if (c < 7 || has_next) { asm volatile("cp.async.wait_group 1;" ::: "memory"); }
        else                   { asm volatile("cp.async.wait_group 0;" ::: "memory"); }
        __syncthreads();
        const uint32_t buf = sb + WBUF_OFF + (c&1)*WCH;
#pragma unroll
        for (int ks = 0; ks < 2; ++ks) {
            uint32_t a[2][4];
#pragma unroll
            for (int mt = 0; mt < 2; ++mt) {
                const uint32_t ro = (uint32_t)((m0 + mt*16 + row_a)*LDA + c*32 + ks*16 + k_a)*2;
                ldsm4(a[mt], sb + A_OFF + ro);
            }
#pragma unroll
            for (int ng = 0; ng < 4; ++ng) {
                uint32_t bb[4];
                ldsm4(bb, buf + (uint32_t)((n0 + ng*16 + n_b)*LDB + ks*16 + k_b)*2);
#pragma unroll
                for (int mt = 0; mt < 2; ++mt) {
                    mma16816(acc[mt][2*ng],   a[mt], bb[0], bb[1]);
                    mma16816(acc[mt][2*ng+1], a[mt], bb[2], bb[3]);
                }
            }
        }
        __syncthreads();
    }
}

__global__ void __launch_bounds__(256,2)
occ_mma_kernel(const float* __restrict__ ray_points,
               const float* __restrict__ translations,
               const float* __restrict__ scale,
               const float* __restrict__ Wp, const float* __restrict__ bp,
               const float* __restrict__ b1, const float* __restrict__ b2,
               const float* __restrict__ Wout, const float* __restrict__ bout,
               float* __restrict__ out)
{
    extern __shared__ __align__(16) unsigned char smem[];
    const uint32_t sb = smem_u32(smem);
    float* sCond= (float*)(smem + COND_OFF);
    float* sWp  = (float*)(smem + WP_OFF);
    float* sbp  = (float*)(smem + BP_OFF);
    float* sb1  = (float*)(smem + B1_OFF);
    float* sb2  = (float*)(smem + B2_OFF);
    float* sWo  = (float*)(smem + WO_OFF);
    float* sXt  = (float*)(smem + XT_OFF);
    float* sFell= (float*)(smem + FELL_OFF);
    int*   sMi  = (int*)  (smem + MI_OFF);
    float* sP   = (float*)(smem + SP_OFF);

    const int t = threadIdx.x;
    const int w = t >> 5, l = t & 31;
    const int m0 = (w >> 2) * 32;           // 2 row groups x 32
    const int cg = w & 3;
    const int n0 = cg * 64;                 // 4 col groups x 64
    const int li = l & 7, grp = l >> 3;
    const int row_a = li + ((grp & 1) << 3);
    const int k_a   = (grp >> 1) << 3;
    const int n_b   = li + ((grp >> 1) << 3);
    const int k_b   = (grp & 1) << 3;

    const int item0 = blockIdx.x * TILE;
    const int b = item0 >> 17;

    prefetch_chunk(sb + WBUF_OFF, 0, 0, t);

    sWp[t]=Wp[t]; sWp[256+t]=Wp[256+t]; sWp[512+t]=Wp[512+t];
    sbp[t]=bp[t]; sb1[t]=b1[t]; sb2[t]=b2[t]; sWo[t]=Wout[t];

    // stage cond for this b: [m][j] with padded stride LDC
#pragma unroll
    for (int i = 0; i < 16; ++i) {
        const int idx = i*256 + t;
        sCond[(idx >> 8)*LDC + (idx & 255)] = g_cond[b*(MM*HH) + idx];
    }

    if (t < TILE) {
        const int item = item0 + t;
        const int rem = item & (NPTS*MM - 1);
        const int np_ = rem >> 4, m = rem & 15, bm = b*MM + m;
        const float px=ray_points[(b*NPTS+np_)*3], py=ray_points[(b*NPTS+np_)*3+1], pz=ray_points[(b*NPTS+np_)*3+2];
        const float cx=px-translations[bm*3], cy=py-translations[bm*3+1], cz=pz-translations[bm*3+2];
        const float* R = g_R + bm*9;
        const float x0=R[0]*cx+R[1]*cy+R[2]*cz;
        const float x1=R[3]*cx+R[4]*cy+R[5]*cz;
        const float x2=R[6]*cx+R[7]*cy+R[8]*cz;
        const float q0=x0/scale[bm*3], q1=x1/scale[bm*3+1], q2=x2/scale[bm*3+2];
        sXt[t*3]=x0; sXt[t*3+1]=x1; sXt[t*3+2]=x2;
        sFell[t]=q0*q0+q1*q1+q2*q2; sMi[t]=m;
    }
    __syncthreads();

    // Build A0 = relu(net0) as fp16. Thread t: row r=t>>2, quarter q=t&3 (64 cols).
    {
        const int r = t >> 2, q = t & 3;
        const float x0=sXt[r*3], x1=sXt[r*3+1], x2=sXt[r*3+2];
        const float* cond = sCond + sMi[r]*LDC;
        uint32_t* dA = (uint32_t*)(smem + A_OFF + (r*LDA + q*64)*2);
#pragma unroll 8
        for (int jj = 0; jj < 32; ++jj) {
            const int j = q*64 + 2*jj;
            float v0 = fmaf(x0,sWp[j],  fmaf(x1,sWp[256+j],  fmaf(x2,sWp[512+j],  sbp[j]  +cond[j])));
            float v1 = fmaf(x0,sWp[j+1],fmaf(x1,sWp[256+j+1],fmaf(x2,sWp[512+j+1],sbp[j+1]+cond[j+1])));
            __half2 hp = __floats2half2_rn(fmaxf(v0,0.f), fmaxf(v1,0.f));
            dA[jj] = *reinterpret_cast<uint32_t*>(&hp);
        }
    }
    __syncthreads();

    float acc[2][8][4];
#pragma unroll
    for (int a=0;a<2;++a)
#pragma unroll
        for (int c=0;c<8;++c)
#pragma unroll
            for (int k=0;k<4;++k) acc[a][c][k]=0.f;

    // ---- GEMM1 ----
    gemm_layer(0, 1, sb, acc, t, m0, n0, row_a, k_a, n_b, k_b);

    // Epilogue1: A1 = relu(acc + b1) -> fp16 -> A smem
#pragma unroll
    for (int mt = 0; mt < 2; ++mt) {
#pragma unroll
        for (int nt = 0; nt < 8; ++nt) {
            const int j0 = n0 + nt*8 + ((l&3)<<1);
            const int r0 = m0 + mt*16 + (l>>2);
            __half2 hA = __floats2half2_rn(fmaxf(acc[mt][nt][0] + sb1[j0],   0.f),
                                           fmaxf(acc[mt][nt][1] + sb1[j0+1], 0.f));
            __half2 hB = __floats2half2_rn(fmaxf(acc[mt][nt][2] + sb1[j0],   0.f),
                                           fmaxf(acc[mt][nt][3] + sb1[j0+1], 0.f));
            *(uint32_t*)(smem + A_OFF + (r0*LDA + j0)*2)     = *reinterpret_cast<uint32_t*>(&hA);
            *(uint32_t*)(smem + A_OFF + ((r0+8)*LDA + j0)*2) = *reinterpret_cast<uint32_t*>(&hB);
            acc[mt][nt][0]=0.f; acc[mt][nt][1]=0.f; acc[mt][nt][2]=0.f; acc[mt][nt][3]=0.f;
        }
    }
    __syncthreads();

    // ---- GEMM2 ----
    gemm_layer(1, 0, sb, acc, t, m0, n0, row_a, k_a, n_b, k_b);

    // Final epilogue: net = net0 + acc + b2; p = sum relu(net)*Wout
    {
        float X0[2][2], X1[2][2], X2[2][2];
        int   Mi[2][2];
#pragma unroll
        for (int mt = 0; mt < 2; ++mt)
#pragma unroll
            for (int h = 0; h < 2; ++h) {
                const int r = m0 + mt*16 + (l>>2) + h*8;
                X0[mt][h]=sXt[r*3]; X1[mt][h]=sXt[r*3+1]; X2[mt][h]=sXt[r*3+2];
                Mi[mt][h]=sMi[r];
            }
        float ps[2][2] = {{0.f,0.f},{0.f,0.f}};
#pragma unroll
        for (int mt = 0; mt < 2; ++mt) {
#pragma unroll
            for (int nt = 0; nt < 8; ++nt) {
                const int j0 = n0 + nt*8 + ((l&3)<<1);
#pragma unroll
                for (int k = 0; k < 4; ++k) {
                    const int j = j0 + (k & 1);
                    const int h = k >> 1;
                    const float cnd = sCond[Mi[mt][h]*LDC + j];
                    float net0 = fmaf(X0[mt][h],sWp[j],
                                 fmaf(X1[mt][h],sWp[256+j],
                                 fmaf(X2[mt][h],sWp[512+j], sbp[j] + cnd)));
                    float net = net0 + acc[mt][nt][k] + sb2[j];
                    ps[mt][h] = fmaf(fmaxf(net,0.f), sWo[j], ps[mt][h]);
                }
            }
        }
#pragma unroll
        for (int mt = 0; mt < 2; ++mt)
#pragma unroll
            for (int h = 0; h < 2; ++h) {
                float p = ps[mt][h];
                p += __shfl_xor_sync(0xffffffffu, p, 1);
                p += __shfl_xor_sync(0xffffffffu, p, 2);
                if ((l & 3) == 0) {
                    const int r = m0 + mt*16 + (l>>2) + h*8;
                    sP[r*4 + cg] = p;
                }
            }
    }
    __syncthreads();
    if (t < TILE) {
        const float occ = sP[t*4] + sP[t*4+1] + sP[t*4+2] + sP[t*4+3] + bout[0];
        const float F   = (sFell[t] <= 1.0f) ? occ : -100.0f;
        out[item0 + t]  = 1.0f / (1.0f + expf(-10.0f * F));
    }
}

// ---------------- launch ----------------
extern "C" void kernel_launch(void* const* d_in, const int* in_sizes, int n_in,
                              void* d_out, int out_size)
{
    const float* ray_points   = (const float*)d_in[0];
    const float* translations = (const float*)d_in[1];
    const float* rotations    = (const float*)d_in[2];
    const float* scale        = (const float*)d_in[3];
    const float* psf          = (const float*)d_in[4];
    const float* Wp   = (const float*)d_in[5];
    const float* bp   = (const float*)d_in[6];
    const float* Wc   = (const float*)d_in[7];
    const float* bc   = (const float*)d_in[8];
    const float* W1   = (const float*)d_in[9];
    const float* b1   = (const float*)d_in[10];
    const float* W2   = (const float*)d_in[11];
    const float* b2   = (const float*)d_in[12];
    const float* Wout = (const float*)d_in[13];
    const float* bout = (const float*)d_in[14];
    float*       out  = (float*)d_out;

    cudaFuncSetAttribute(occ_mma_kernel,
                         cudaFuncAttributeMaxDynamicSharedMemorySize, SMEM_BYTES);

    prologue_kernel<<<544, 256>>>(rotations, psf, Wc, bc, W1, W2);
    occ_mma_kernel<<<NBLK, 256, SMEM_BYTES>>>(ray_points, translations, scale,
                                              Wp, bp, b1, b2, Wout, bout, out);
}

// round 17
// speedup vs baseline: 2.8810x; 1.0203x over previous
#include <cuda_runtime.h>
#include <cuda_fp16.h>
#include <math.h>
#include <stdint.h>

#define BD 2
#define NPTS 8192
#define MM 16
#define HH 256
#define CC 128
#define ITEMS (BD*NPTS*MM)
#define TILE 64
#define NBLK (ITEMS/TILE)        // 4096
#define LDA 264                  // A smem row stride (fp16 elements)
#define LDB 40                   // W chunk row stride (fp16 elements)
#define WCH 20480                // one weight chunk buffer (256 rows x 80B)
#define LDC 264                  // sCond row stride (fp32 words)

// smem offsets (bytes)
#define A_OFF    0               // 64*264*2 = 33792
#define WBUF_OFF 33792           // 2 x 20480 = 40960
#define COND_OFF 74752           // 16*264*4 = 16896
#define WP_OFF   91648           // 3*256*4
#define BP_OFF   94720
#define B1_OFF   95744
#define B2_OFF   96768
#define WO_OFF   97792
#define XT_OFF   98816           // 64*3*4
#define FELL_OFF 99584
#define MI_OFF   99840
#define SP_OFF   100096          // 64*4*4
#define SMEM_BYTES 101120

__device__ float g_cond[BD*MM*HH];   // [bm][j]
__device__ float g_R[BD*MM*9];
// W fp16: [layer][n][k]; layer stride 131072B, n-row 512B
__device__ __align__(16) unsigned char g_Wh[2*256*256*2];

// ---------------- PTX helpers ----------------
__device__ __forceinline__ uint32_t smem_u32(const void* p){
    uint32_t a;
    asm("{ .reg .u64 t; cvta.to.shared.u64 t, %1; cvt.u32.u64 %0, t; }":"=r"(a):"l"(p));
    return a;
}
__device__ __forceinline__ void ldsm4(uint32_t* r, uint32_t addr){
    asm volatile("ldmatrix.sync.aligned.m8n8.x4.shared.b16 {%0,%1,%2,%3}, [%4];"
        : "=r"(r[0]),"=r"(r[1]),"=r"(r[2]),"=r"(r[3]) : "r"(addr));
}
__device__ __forceinline__ void mma16816(float* d, const uint32_t* a, uint32_t b0, uint32_t b1){
    asm volatile("mma.sync.aligned.m16n8k16.row.col.f32.f16.f16.f32 "
        "{%0,%1,%2,%3}, {%4,%5,%6,%7}, {%8,%9}, {%0,%1,%2,%3};"
        : "+f"(d[0]),"+f"(d[1]),"+f"(d[2]),"+f"(d[3])
        : "r"(a[0]),"r"(a[1]),"r"(a[2]),"r"(a[3]), "r"(b0),"r"(b1));
}

// ---------------- merged prologue ----------------
// blocks 0..31: cond + rotation. blocks 32..543: W1/W2 -> [n][k] fp16.
__global__ void prologue_kernel(const float* __restrict__ rotations,
                                const float* __restrict__ psf,
                                const float* __restrict__ Wc,
                                const float* __restrict__ bc,
                                const float* __restrict__ W1,
                                const float* __restrict__ W2)
{
    const int t = threadIdx.x;
    if (blockIdx.x < 32) {
        __shared__ float s_psf[CC];
        const int bm = blockIdx.x;
        if (t < CC) s_psf[t] = psf[bm*CC + t];
        __syncthreads();
        float acc = bc[t];
#pragma unroll 8
        for (int k = 0; k < CC; ++k) acc = fmaf(s_psf[k], Wc[k*HH + t], acc);
        g_cond[bm*HH + t] = acc;
        if (t == 0) {
            float w=rotations[bm*4],x=rotations[bm*4+1],y=rotations[bm*4+2],z=rotations[bm*4+3];
            float inv = rsqrtf(w*w+x*x+y*y+z*z);
            w*=inv; x*=inv; y*=inv; z*=inv;
            float* R = g_R + bm*9;
            R[0]=1.f-2.f*(y*y+z*z); R[1]=2.f*(x*y-w*z); R[2]=2.f*(x*z+w*y);
            R[3]=2.f*(x*y+w*z); R[4]=1.f-2.f*(x*x+z*z); R[5]=2.f*(y*z-w*x);
            R[6]=2.f*(x*z-w*y); R[7]=2.f*(y*z+w*x); R[8]=1.f-2.f*(x*x+y*y);
        }
    } else {
        const int idx = (blockIdx.x - 32)*256 + t;   // 0..131071
        const int layer = idx >> 16;
        const int e = idx & 65535;
        const int k = e >> 8, n = e & 255;
        const float v = (layer ? W2 : W1)[k*HH + n];
        size_t o = ((size_t)layer*256 + n)*256 + k;
        *(__half*)(g_Wh + o*2) = __float2half_rn(v);
    }
}

// ---------------- main kernel ----------------
// one k-chunk: 32 k x 256 n fp16 = 16KB; 256 threads x 4 x 16B
__device__ __forceinline__ void prefetch_chunk(uint32_t dst, int layer, int c, int t){
#pragma unroll
    for (int i = 0; i < 4; ++i) {
        const int idx = t*4 + i;                 // 0..1023
        const int n   = idx >> 2;
        const int seg = idx & 3;
        const unsigned char* src = g_Wh + (size_t)layer*131072
                                 + (size_t)n*512 + c*64 + seg*16;
        const uint32_t d = dst + n*(LDB*2) + seg*16;
        asm volatile("cp.async.cg.shared.global [%0], [%1], 16;" :: "r"(d), "l"(src));
    }
    asm volatile("cp.async.commit_group;" ::: "memory");
}

// Single barrier per chunk:
//   wait_group 0   -> my slices of chunk c (issued last iter) have landed
//   __syncthreads  -> (a) everyone's slices landed: buffer c is ready
//                     (b) every warp has consumed its chunk c-1 ldsm data
//                         (dependent HMMAs force LDSM completion pre-barrier)
//   prefetch c+1 into the other buffer  (safe after the barrier)
//   compute chunk c
__device__ __forceinline__ void gemm_layer(int layer, int has_next, uint32_t sb,
    float acc[2][8][4], int t, int m0, int n0, int row_a, int k_a, int n_b, int k_b)
{
    for (int c = 0; c < 8; ++c) {
        const int g = layer*8 + c;
        asm volatile("cp.async.wait_group 0;" ::: "memory");
        __syncthreads();
        if (c < 7)         prefetch_chunk(sb + WBUF_OFF + ((g+1)&1)*WCH, layer,   c+1, t);
        else if (has_next) prefetch_chunk(sb + WBUF_OFF + ((g+1)&1)*WCH, layer+1, 0,   t);
        const uint32_t buf = sb + WBUF_OFF + (g&1)*WCH;
#pragma unroll
        for (int ks = 0; ks < 2; ++ks) {
            uint32_t a[2][4];
#pragma unroll
            for (int mt = 0; mt < 2; ++mt) {
                const uint32_t ro = (uint32_t)((m0 + mt*16 + row_a)*LDA + c*32 + ks*16 + k_a)*2;
                ldsm4(a[mt], sb + A_OFF + ro);
            }
#pragma unroll
            for (int ng = 0; ng < 4; ++ng) {
                uint32_t bb[4];
                ldsm4(bb, buf + (uint32_t)((n0 + ng*16 + n_b)*LDB + ks*16 + k_b)*2);
#pragma unroll
                for (int mt = 0; mt < 2; ++mt) {
                    mma16816(acc[mt][2*ng],   a[mt], bb[0], bb[1]);
                    mma16816(acc[mt][2*ng+1], a[mt], bb[2], bb[3]);
                }
            }
        }
    }
}

__global__ void __launch_bounds__(256,2)
occ_mma_kernel(const float* __restrict__ ray_points,
               const float* __restrict__ translations,
               const float* __restrict__ scale,
               const float* __restrict__ Wp, const float* __restrict__ bp,
               const float* __restrict__ b1, const float* __restrict__ b2,
               const float* __restrict__ Wout, const float* __restrict__ bout,
               float* __restrict__ out)
{
    extern __shared__ __align__(16) unsigned char smem[];
    const uint32_t sb = smem_u32(smem);
    float* sCond= (float*)(smem + COND_OFF);
    float* sWp  = (float*)(smem + WP_OFF);
    float* sbp  = (float*)(smem + BP_OFF);
    float* sb1  = (float*)(smem + B1_OFF);
    float* sb2  = (float*)(smem + B2_OFF);
    float* sWo  = (float*)(smem + WO_OFF);
    float* sXt  = (float*)(smem + XT_OFF);
    float* sFell= (float*)(smem + FELL_OFF);
    int*   sMi  = (int*)  (smem + MI_OFF);
    float* sP   = (float*)(smem + SP_OFF);

    const int t = threadIdx.x;
    const int w = t >> 5, l = t & 31;
    const int m0 = (w >> 2) * 32;           // 2 row groups x 32
    const int cg = w & 3;
    const int n0 = cg * 64;                 // 4 col groups x 64
    const int li = l & 7, grp = l >> 3;
    const int row_a = li + ((grp & 1) << 3);
    const int k_a   = (grp >> 1) << 3;
    const int n_b   = li + ((grp >> 1) << 3);
    const int k_b   = (grp & 1) << 3;

    const int item0 = blockIdx.x * TILE;
    const int b = item0 >> 17;

    prefetch_chunk(sb + WBUF_OFF, 0, 0, t);   // chunk g=0 into buf0

    sWp[t]=Wp[t]; sWp[256+t]=Wp[256+t]; sWp[512+t]=Wp[512+t];
    sbp[t]=bp[t]; sb1[t]=b1[t]; sb2[t]=b2[t]; sWo[t]=Wout[t];

    // stage cond for this b: [m][j] with padded stride LDC
#pragma unroll
    for (int i = 0; i < 16; ++i) {
        const int idx = i*256 + t;
        sCond[(idx >> 8)*LDC + (idx & 255)] = g_cond[b*(MM*HH) + idx];
    }

    if (t < TILE) {
        const int item = item0 + t;
        const int rem = item & (NPTS*MM - 1);
        const int np_ = rem >> 4, m = rem & 15, bm = b*MM + m;
        const float px=ray_points[(b*NPTS+np_)*3], py=ray_points[(b*NPTS+np_)*3+1], pz=ray_points[(b*NPTS+np_)*3+2];
        const float cx=px-translations[bm*3], cy=py-translations[bm*3+1], cz=pz-translations[bm*3+2];
        const float* R = g_R + bm*9;
        const float x0=R[0]*cx+R[1]*cy+R[2]*cz;
        const float x1=R[3]*cx+R[4]*cy+R[5]*cz;
        const float x2=R[6]*cx+R[7]*cy+R[8]*cz;
        const float q0=x0/scale[bm*3], q1=x1/scale[bm*3+1], q2=x2/scale[bm*3+2];
        sXt[t*3]=x0; sXt[t*3+1]=x1; sXt[t*3+2]=x2;
        sFell[t]=q0*q0+q1*q1+q2*q2; sMi[t]=m;
    }
    __syncthreads();   // geometry/staging -> A-build

    // Build A0 = relu(net0) as fp16. Thread t: row r=t>>2, quarter q=t&3 (64 cols).
    {
        const int r = t >> 2, q = t & 3;
        const float x0=sXt[r*3], x1=sXt[r*3+1], x2=sXt[r*3+2];
        const float* cond = sCond + sMi[r]*LDC;
        uint32_t* dA = (uint32_t*)(smem + A_OFF + (r*LDA + q*64)*2);
#pragma unroll 8
        for (int jj = 0; jj < 32; ++jj) {
            const int j = q*64 + 2*jj;
            float v0 = fmaf(x0,sWp[j],  fmaf(x1,sWp[256+j],  fmaf(x2,sWp[512+j],  sbp[j]  +cond[j])));
            float v1 = fmaf(x0,sWp[j+1],fmaf(x1,sWp[256+j+1],fmaf(x2,sWp[512+j+1],sbp[j+1]+cond[j+1])));
            __half2 hp = __floats2half2_rn(fmaxf(v0,0.f), fmaxf(v1,0.f));
            dA[jj] = *reinterpret_cast<uint32_t*>(&hp);
        }
    }
    // NOTE: no sync here — gemm1's first in-loop barrier orders A stores vs ldsm.

    float acc[2][8][4];
#pragma unroll
    for (int a=0;a<2;++a)
#pragma unroll
        for (int c=0;c<8;++c)
#pragma unroll
            for (int k=0;k<4;++k) acc[a][c][k]=0.f;

    // ---- GEMM1 ----
    gemm_layer(0, 1, sb, acc, t, m0, n0, row_a, k_a, n_b, k_b);

    __syncthreads();   // gemm1's last A reads -> epilogue1 A writes

    // Epilogue1: A1 = relu(acc + b1) -> fp16 -> A smem
#pragma unroll
    for (int mt = 0; mt < 2; ++mt) {
#pragma unroll
        for (int nt = 0; nt < 8; ++nt) {
            const int j0 = n0 + nt*8 + ((l&3)<<1);
            const int r0 = m0 + mt*16 + (l>>2);
            __half2 hA = __floats2half2_rn(fmaxf(acc[mt][nt][0] + sb1[j0],   0.f),
                                           fmaxf(acc[mt][nt][1] + sb1[j0+1], 0.f));
            __half2 hB = __floats2half2_rn(fmaxf(acc[mt][nt][2] + sb1[j0],   0.f),
                                           fmaxf(acc[mt][nt][3] + sb1[j0+1], 0.f));
            *(uint32_t*)(smem + A_OFF + (r0*LDA + j0)*2)     = *reinterpret_cast<uint32_t*>(&hA);
            *(uint32_t*)(smem + A_OFF + ((r0+8)*LDA + j0)*2) = *reinterpret_cast<uint32_t*>(&hB);
            acc[mt][nt][0]=0.f; acc[mt][nt][1]=0.f; acc[mt][nt][2]=0.f; acc[mt][nt][3]=0.f;
        }
    }
    // NOTE: no sync here — gemm2's first in-loop barrier orders A1 stores vs ldsm.

    // ---- GEMM2 ----
    gemm_layer(1, 0, sb, acc, t, m0, n0, row_a, k_a, n_b, k_b);

    // Final epilogue: net = net0 + acc + b2; p = sum relu(net)*Wout
    {
        float X0[2][2], X1[2][2], X2[2][2];
        int   Mi[2][2];
#pragma unroll
        for (int mt = 0; mt < 2; ++mt)
#pragma unroll
            for (int h = 0; h < 2; ++h) {
                const int r = m0 + mt*16 + (l>>2) + h*8;
                X0[mt][h]=sXt[r*3]; X1[mt][h]=sXt[r*3+1]; X2[mt][h]=sXt[r*3+2];
                Mi[mt][h]=sMi[r];
            }
        float ps[2][2] = {{0.f,0.f},{0.f,0.f}};
#pragma unroll
        for (int mt = 0; mt < 2; ++mt) {
#pragma unroll
            for (int nt = 0; nt < 8; ++nt) {
                const int j0 = n0 + nt*8 + ((l&3)<<1);
#pragma unroll
                for (int k = 0; k < 4; ++k) {
                    const int j = j0 + (k & 1);
                    const int h = k >> 1;
                    const float cnd = sCond[Mi[mt][h]*LDC + j];
                    float net0 = fmaf(X0[mt][h],sWp[j],
                                 fmaf(X1[mt][h],sWp[256+j],
                                 fmaf(X2[mt][h],sWp[512+j], sbp[j] + cnd)));
                    float net = net0 + acc[mt][nt][k] + sb2[j];
                    ps[mt][h] = fmaf(fmaxf(net,0.f), sWo[j], ps[mt][h]);
                }
            }
        }
#pragma unroll
        for (int mt = 0; mt < 2; ++mt)
#pragma unroll
            for (int h = 0; h < 2; ++h) {
                float p = ps[mt][h];
                p += __shfl_xor_sync(0xffffffffu, p, 1);
                p += __shfl_xor_sync(0xffffffffu, p, 2);
                if ((l & 3) == 0) {
                    const int r = m0 + mt*16 + (l>>2) + h*8;
                    sP[r*4 + cg] = p;
                }
            }
    }
    __syncthreads();
    if (t < TILE) {
        const float occ = sP[t*4] + sP[t*4+1] + sP[t*4+2] + sP[t*4+3] + bout[0];
        const float F   = (sFell[t] <= 1.0f) ? occ : -100.0f;
        out[item0 + t]  = 1.0f / (1.0f + expf(-10.0f * F));
    }
}

// ---------------- launch ----------------
extern "C" void kernel_launch(void* const* d_in, const int* in_sizes, int n_in,
                              void* d_out, int out_size)
{
    const float* ray_points   = (const float*)d_in[0];
    const float* translations = (const float*)d_in[1];
    const float* rotations    = (const float*)d_in[2];
    const float* scale        = (const float*)d_in[3];
    const float* psf          = (const float*)d_in[4];
    const float* Wp   = (const float*)d_in[5];
    const float* bp   = (const float*)d_in[6];
    const float* Wc   = (const float*)d_in[7];
    const float* bc   = (const float*)d_in[8];
    const float* W1   = (const float*)d_in[9];
    const float* b1   = (const float*)d_in[10];
    const float* W2   = (const float*)d_in[11];
    const float* b2   = (const float*)d_in[12];
    const float* Wout = (const float*)d_in[13];
    const float* bout = (const float*)d_in[14];
    float*       out  = (float*)d_out;

    cudaFuncSetAttribute(occ_mma_kernel,
                         cudaFuncAttributeMaxDynamicSharedMemorySize, SMEM_BYTES);

    prologue_kernel<<<544, 256>>>(rotations, psf, Wc, bc, W1, W2);
    occ_mma_kernel<<<NBLK, 256, SMEM_BYTES>>>(ray_points, translations, scale,
                                              Wp, bp, b1, b2, Wout, bout, out);
}